// round 13
// baseline (speedup 1.0000x reference)
#include <cuda_runtime.h>
#include <math.h>

// Problem constants (fixed by the dataset)
#define B_   4
#define LP_  256
#define LW_  200
#define D_   768
#define D4_  (D_/4)      // 192 float4 per row
#define NCH_ 37          // word-chunks per batch (15 chunks of 6 + 22 chunks of 5)
#define WMAX_ 6
#define NT_  768         // 4 group-quarters x 192 d-slots

#define MIN_BLOCKS 148
#define MIN_THREADS 1024

__device__ float g_partial_min[MIN_BLOCKS];

// ---------------- global-min partial reduction ----------------
__global__ __launch_bounds__(MIN_THREADS) void partial_min_kernel(
    const float4* __restrict__ x, int n4)
{
    const int stride = MIN_BLOCKS * MIN_THREADS;
    int i = blockIdx.x * MIN_THREADS + threadIdx.x;
    float m = INFINITY;
    if (i < n4) {
        float4 v = x[i];
        m = fminf(fminf(v.x, v.y), fminf(v.z, v.w));
    }
    i += stride;
    if (i < n4) {
        float4 v = x[i];
        m = fminf(m, fminf(fminf(v.x, v.y), fminf(v.z, v.w)));
    }
    #pragma unroll
    for (int off = 16; off > 0; off >>= 1)
        m = fminf(m, __shfl_xor_sync(0xFFFFFFFFu, m, off));

    __shared__ float s[32];
    const int wid = threadIdx.x >> 5;
    const int lid = threadIdx.x & 31;
    if (lid == 0) s[wid] = m;
    __syncthreads();
    if (wid == 0) {
        m = s[lid];
        #pragma unroll
        for (int off = 16; off > 0; off >>= 1)
            m = fminf(m, __shfl_xor_sync(0xFFFFFFFFu, m, off));
        if (lid == 0) g_partial_min[blockIdx.x] = m;
    }
}

// Process groups g = Q + 4u (u=0..15). Q is compile-time, so after unrolling
// the apply step has compile-time bit tests: exactly popc(g)*4 FMNMX, no
// predication waste, no mask logic.
template<int Q>
__device__ __forceinline__ void process_groups(
    const float4* __restrict__ erow,
    const unsigned char* gflat,
    const int* goff,
    float4* acc)
{
    #pragma unroll
    for (int u = 0; u < 16; u++) {
        const int g = Q + 4 * u;
        if (g == 0) continue;               // mask-0 pieces touch no word
        const int s = goff[g];
        const int e = goff[g + 1];
        if (s < e) {                        // block-uniform branch
            int idx = gflat[s];
            float4 t = erow[(size_t)idx * D4_];
            #pragma unroll 2
            for (int k = s + 1; k < e; k++) {
                int i2 = gflat[k];
                float4 v = erow[(size_t)i2 * D4_];
                t.x = fmaxf(t.x, v.x); t.y = fmaxf(t.y, v.y);
                t.z = fmaxf(t.z, v.z); t.w = fmaxf(t.w, v.w);
            }
            #pragma unroll
            for (int j = 0; j < WMAX_; j++) {
                if (g & (1 << j)) {         // compile-time
                    acc[j].x = fmaxf(acc[j].x, t.x);
                    acc[j].y = fmaxf(acc[j].y, t.y);
                    acc[j].z = fmaxf(acc[j].z, t.z);
                    acc[j].w = fmaxf(acc[j].w, t.w);
                }
            }
        }
    }
}

// ---------------- main: masked max-pool, mask-grouped ----------------
// grid: 148 blocks = 4 batches x 37 word-chunks. block: 768 threads =
// 4 group-quarters (quarter q owns mask-groups g == q mod 4) x 192 d-slots.
__global__ __launch_bounds__(NT_, 1) void word_max_kernel(
    const float* __restrict__ emb,      // [B, Lp, D]
    const int*   __restrict__ p2w,      // [B, Lw, Lp]
    float*       __restrict__ out)      // [B, Lw, D]
{
    __shared__ float4 sacc[2][WMAX_][D4_];      // quarter partials (36.9 KB)
    __shared__ unsigned char pmask[LP_];
    __shared__ unsigned char gflat[LP_];        // pieces sorted by mask value
    __shared__ int scount[64];
    __shared__ int scursor[64];
    __shared__ int goff[65];
    __shared__ float sgmin;

    const int tid = threadIdx.x;
    const int blk = blockIdx.x;
    const int b   = blk / NCH_;
    const int c   = blk % NCH_;
    const int w0  = (c < 15) ? c * 6 : 90 + (c - 15) * 5;
    const int nw  = (c < 15) ? 6 : 5;

    if (tid < 64) scount[tid] = 0;
    __syncthreads();

    // pass 1: per-piece 6-bit mask + group counts; warp 8 folds global min
    if (tid < LP_) {
        const int p = tid;
        const int* row = p2w + ((size_t)(b * LW_ + w0)) * LP_ + p;
        unsigned m = 0;
        #pragma unroll
        for (int j = 0; j < WMAX_; j++)
            if (j < nw && row[(size_t)j * LP_] != 0) m |= (1u << j);
        pmask[p] = (unsigned char)m;
        atomicAdd(&scount[m], 1);
    } else if (tid < 288) {
        const int l = tid - 256;
        float m = INFINITY;
        for (int k = l; k < MIN_BLOCKS; k += 32)
            m = fminf(m, g_partial_min[k]);
        #pragma unroll
        for (int off = 16; off > 0; off >>= 1)
            m = fminf(m, __shfl_xor_sync(0xFFFFFFFFu, m, off));
        if (l == 0) sgmin = m;
    }
    __syncthreads();

    // exclusive prefix sum of 64 counts (warp 0, 2 values per lane)
    if (tid < 32) {
        int c0 = scount[2 * tid], c1 = scount[2 * tid + 1];
        int sum = c0 + c1;
        int inc = sum;
        #pragma unroll
        for (int off = 1; off < 32; off <<= 1) {
            int n = __shfl_up_sync(0xFFFFFFFFu, inc, off);
            if (tid >= off) inc += n;
        }
        int base = inc - sum;
        goff[2 * tid]     = base;
        goff[2 * tid + 1] = base + c0;
        scursor[2 * tid]     = base;
        scursor[2 * tid + 1] = base + c0;
        if (tid == 31) goff[64] = inc;          // = 256
    }
    __syncthreads();

    // pass 2: scatter piece ids into group-sorted flat array
    if (tid < LP_) {
        int m = pmask[tid];
        int slot = atomicAdd(&scursor[m], 1);
        gflat[slot] = (unsigned char)tid;
    }
    __syncthreads();

    const float gmin = sgmin;
    const int q  = tid / D4_;        // group-quarter 0..3 (warp-aligned)
    const int dt = tid % D4_;        // float4 slot in D

    float4 acc[WMAX_];
    #pragma unroll
    for (int j = 0; j < WMAX_; j++) acc[j] = make_float4(gmin, gmin, gmin, gmin);

    const float4* erow = reinterpret_cast<const float4*>(emb)
                         + (size_t)b * LP_ * D4_ + dt;

    switch (q) {
        case 0:  process_groups<0>(erow, gflat, goff, acc); break;
        case 1:  process_groups<1>(erow, gflat, goff, acc); break;
        case 2:  process_groups<2>(erow, gflat, goff, acc); break;
        default: process_groups<3>(erow, gflat, goff, acc); break;
    }

    // --- combine quarters: {2,3} -> smem; {0,1} merge; 1 -> smem; 0 final ---
    if (q >= 2) {
        #pragma unroll
        for (int j = 0; j < WMAX_; j++) sacc[q - 2][j][dt] = acc[j];
    }
    __syncthreads();
    if (q < 2) {
        #pragma unroll
        for (int j = 0; j < WMAX_; j++) {
            float4 o = sacc[q][j][dt];
            acc[j].x = fmaxf(acc[j].x, o.x);
            acc[j].y = fmaxf(acc[j].y, o.y);
            acc[j].z = fmaxf(acc[j].z, o.z);
            acc[j].w = fmaxf(acc[j].w, o.w);
        }
        if (q == 1) {
            #pragma unroll
            for (int j = 0; j < WMAX_; j++) sacc[1][j][dt] = acc[j];
        }
    }
    __syncthreads();
    if (q == 0) {
        float4* out4 = reinterpret_cast<float4*>(out)
                       + ((size_t)(b * LW_ + w0)) * D4_ + dt;
        #pragma unroll
        for (int j = 0; j < WMAX_; j++) {
            if (j < nw) {
                float4 o = sacc[1][j][dt];
                o.x = fmaxf(o.x, acc[j].x);
                o.y = fmaxf(o.y, acc[j].y);
                o.z = fmaxf(o.z, acc[j].z);
                o.w = fmaxf(o.w, acc[j].w);
                out4[(size_t)j * D4_] = o;
            }
        }
    }
}

extern "C" void kernel_launch(void* const* d_in, const int* in_sizes, int n_in,
                              void* d_out, int out_size) {
    const float* emb = (const float*)d_in[0];   // [4,256,768] f32
    const int*   p2w = (const int*)d_in[1];     // [4,200,256] i32
    float*       out = (float*)d_out;           // [4,200,768] f32

    const int n4 = (B_ * LP_ * D_) / 4;         // 196608
    partial_min_kernel<<<MIN_BLOCKS, MIN_THREADS>>>((const float4*)emb, n4);
    word_max_kernel<<<B_ * NCH_, NT_>>>(emb, p2w, out);
}